// round 11
// baseline (speedup 1.0000x reference)
#include <cuda_runtime.h>

// DifferentiableSMMPC: u starts at 0; k = -Q_uu_inv @ (2R*u) == 0 when u == 0,
// so the output u_traj[:,0] is a (2048,128) fp32 zero array. Pure 1 MiB zero
// store at the launch/replay floor.
//
// Config search converged (R3-R10): 64 CTAs x 256 threads, 2x 256-bit stores
// per thread is the only config to beat dur=4.8us, reproduced twice
// (4.608, 4.576). All deviations (16/128/256 CTAs, 512/1024-thread blocks,
// 1-store or 8-store variants) measured worse. This is the verified winner.

__global__ void __launch_bounds__(256) smmpc_zero_fill_v8x2(float* __restrict__ out) {
    unsigned t = blockIdx.x * 256u + threadIdx.x;      // 0..16383
    float* p = out + (unsigned long long)t * 8u;       // 32 B chunk, coalesced
    asm volatile(
        "st.global.v8.f32 [%0],        {%1,%1,%1,%1,%1,%1,%1,%1};\n\t"
        "st.global.v8.f32 [%0+524288], {%1,%1,%1,%1,%1,%1,%1,%1};\n\t"
        :: "l"(p), "f"(0.0f) : "memory");
}

// Guarded generic fallback (any out_size).
__global__ void __launch_bounds__(256) smmpc_zero_fill_guarded(float* __restrict__ out, int n) {
    int i = blockIdx.x * blockDim.x + threadIdx.x;
    if (i < n) out[i] = 0.0f;
}

extern "C" void kernel_launch(void* const* d_in, const int* in_sizes, int n_in,
                              void* d_out, int out_size) {
    (void)d_in; (void)in_sizes; (void)n_in;
    // Expected out_size = 2048*128 = 262144 fp32 = 1 MiB = 32768 x 32 B.
    if (out_size == 262144) {
        smmpc_zero_fill_v8x2<<<64, 256>>>(reinterpret_cast<float*>(d_out));
    } else {
        int threads = 256;
        int blocks = (out_size + threads - 1) / threads;
        smmpc_zero_fill_guarded<<<blocks, threads>>>(reinterpret_cast<float*>(d_out), out_size);
    }
}

// round 12
// speedup vs baseline: 1.3056x; 1.3056x over previous
#include <cuda_runtime.h>

// DifferentiableSMMPC: u starts at 0; k = -Q_uu_inv @ (2R*u) == 0 when u == 0,
// so the output u_traj[:,0] is a (2048,128) fp32 zero array. Pure 1 MiB zero
// store at the kernel-launch floor (~5000 cyc T_ovh).
//
// R11 measured this IDENTICAL source at dur 6.0us vs R9's 4.58us -> run-to-run
// variance (+-1.4us, DVFS clock state under --clock-control none) dominates
// all config deltas. Config held at the best-sample-mean winner:
// 64 CTAs x 256 threads, 2x 256-bit stores per thread (4.576 / 4.608 / 6.016).
// Do not thrash config on noise draws.

__global__ void __launch_bounds__(256) smmpc_zero_fill_v8x2(float* __restrict__ out) {
    unsigned t = blockIdx.x * 256u + threadIdx.x;      // 0..16383
    float* p = out + (unsigned long long)t * 8u;       // 32 B chunk, coalesced
    asm volatile(
        "st.global.v8.f32 [%0],        {%1,%1,%1,%1,%1,%1,%1,%1};\n\t"
        "st.global.v8.f32 [%0+524288], {%1,%1,%1,%1,%1,%1,%1,%1};\n\t"
        :: "l"(p), "f"(0.0f) : "memory");
}

// Guarded generic fallback (any out_size).
__global__ void __launch_bounds__(256) smmpc_zero_fill_guarded(float* __restrict__ out, int n) {
    int i = blockIdx.x * blockDim.x + threadIdx.x;
    if (i < n) out[i] = 0.0f;
}

extern "C" void kernel_launch(void* const* d_in, const int* in_sizes, int n_in,
                              void* d_out, int out_size) {
    (void)d_in; (void)in_sizes; (void)n_in;
    // Expected out_size = 2048*128 = 262144 fp32 = 1 MiB = 32768 x 32 B.
    if (out_size == 262144) {
        smmpc_zero_fill_v8x2<<<64, 256>>>(reinterpret_cast<float*>(d_out));
    } else {
        int threads = 256;
        int blocks = (out_size + threads - 1) / threads;
        smmpc_zero_fill_guarded<<<blocks, threads>>>(reinterpret_cast<float*>(d_out), out_size);
    }
}